// round 15
// baseline (speedup 1.0000x reference)
#include <cuda_runtime.h>
#include <cuda_fp16.h>
#include <math.h>
#include <stdint.h>

#define DIMV 512
#define HIDV 2048
#define NE 16
#define NB 8
#define NN 2048
#define CAPV 256
#define TOK (NB*NN)          // 16384
#define ROWS (NB*CAPV)       // 2048 rows per expert

// ---- static device scratch (no dynamic allocations allowed) ----
__device__ __align__(256) __half g_ei[(size_t)NE*ROWS*DIMV];       // 32 MiB (half)
__device__ __align__(256) __half g_hidden[(size_t)NE*ROWS*HIDV];   // 128 MiB (half)
__device__ __align__(256) float  g_eo[(size_t)NE*ROWS*DIMV];       // 64 MiB
__device__ __align__(256) __half g_w1h[(size_t)NE*HIDV*DIMV];      // 32 MiB  W1^T [E][HID][DIM]
__device__ __align__(256) __half g_w2h[(size_t)NE*DIMV*HIDV];      // 32 MiB  W2^T [E][DIM][HID]
__device__ __align__(256) float  g_weights[(size_t)TOK*NE];
__device__ __align__(256) unsigned int g_maskbits[TOK];
__device__ __align__(256) int    g_pos[(size_t)TOK*NE];
__device__ __align__(256) float  g_proxysum[NB*NE];
__device__ __align__(256) float  g_dcount[NB*NE];
__device__ __align__(256) int    g_hw[NE*NB];       // high-water mark per (e,b): max pos_tok+1

// ---------------- zero scratch ----------------
// g_ei = 16,777,216 halves = 2,097,152 uint4 -> grid 8192 x 256
__global__ void zero_kernel() {
    size_t i = (size_t)blockIdx.x * blockDim.x + threadIdx.x;
    uint4 z = {0u, 0u, 0u, 0u};
    ((uint4*)g_ei)[i] = z;
    if (i < NB*NE) { g_proxysum[i] = 0.f; g_hw[i] = 0; }
}

// ---------------- weight transpose fp32 -> half, K-major ----------------
template <int WHICH>
__global__ void transpose_kernel(const float* __restrict__ src) {
    constexpr int K = (WHICH == 1) ? DIMV : HIDV;
    constexpr int N = (WHICH == 1) ? HIDV : DIMV;
    __half* dst = (WHICH == 1) ? g_w1h : g_w2h;
    int e = blockIdx.z;
    __shared__ float tile[32][33];
    int n0 = blockIdx.x * 32, k0 = blockIdx.y * 32;
    int tx = threadIdx.x, ty = threadIdx.y;      // 32 x 8
    const float* s = src + (size_t)e * K * N;
    __half* d = dst + (size_t)e * N * K;
#pragma unroll
    for (int j = 0; j < 32; j += 8)
        tile[ty + j][tx] = s[(size_t)(k0 + ty + j) * N + n0 + tx];
    __syncthreads();
#pragma unroll
    for (int j = 0; j < 32; j += 8)
        d[(size_t)(n0 + ty + j) * K + k0 + tx] = __float2half_rn(tile[tx][ty + j]);
}

// ---------------- gating: one warp per token, smem-staged x ----------------
// Block = 256 threads = 8 warps = 8 tokens. Lane layout: e = lane&15, h = lane>>4.
__global__ __launch_bounds__(256) void gate_kernel(const float* __restrict__ x,
                                                   const float* __restrict__ wg) {
    const int wid   = threadIdx.x >> 5;
    const int lane  = threadIdx.x & 31;
    const int tok   = blockIdx.x * 8 + wid;
    const int e     = lane & 15;             // expert handled by this lane
    const int h     = lane >> 4;             // dim-half
    const unsigned FULL = 0xffffffffu;

    __shared__ float xs[8][DIMV];            // 16 KB: 8 token rows
    __shared__ float psum[NE];               // block-level proxy accumulation
    if (threadIdx.x < NE) psum[threadIdx.x] = 0.f;

    // coalesced block load of 8 rows (1024 float4)
    {
        const float4* xsrc = (const float4*)(x + (size_t)blockIdx.x * 8 * DIMV);
        float4* xdst = (float4*)&xs[0][0];
#pragma unroll
        for (int i = 0; i < 4; i++)
            xdst[threadIdx.x + i * 256] = xsrc[threadIdx.x + i * 256];
    }
    __syncthreads();

    // ---- logits: each lane: sum over 256 dims of x[d]*wg[d][e] ----
    const float4* xrow = (const float4*)&xs[wid][h * 256];
    const float* wgh = wg + (size_t)h * 256 * NE + e;
    float acc = 0.f;
#pragma unroll 8
    for (int i = 0; i < 64; i++) {
        float4 xv = xrow[i];
        const float* wr = wgh + i * 4 * NE;
        acc += xv.x * wr[0 * NE] + xv.y * wr[1 * NE]
             + xv.z * wr[2 * NE] + xv.w * wr[3 * NE];
    }
    acc += __shfl_xor_sync(FULL, acc, 16);   // both halves now hold logit[e]

    // ---- softmax over 16 lanes (halves mirrored) ----
    float mx = acc;
#pragma unroll
    for (int off = 8; off >= 1; off >>= 1)
        mx = fmaxf(mx, __shfl_xor_sync(FULL, mx, off));
    float raw = expf(acc - mx);
    float ssum = raw;
#pragma unroll
    for (int off = 8; off >= 1; off >>= 1)
        ssum += __shfl_xor_sync(FULL, ssum, off);
    raw /= ssum;                              // raw prob for expert e

    // block-level proxy accumulation (all tokens in block share same b)
    if (lane < NE) atomicAdd(&psum[e], raw);

    // ---- bitonic sort, 16 lanes, stable-descending (tie-break on index) ----
    float p = raw;
    int   oe = e;
    const int l16 = lane & 15;
#pragma unroll
    for (int kk = 2; kk <= 16; kk <<= 1) {
#pragma unroll
        for (int j = kk >> 1; j >= 1; j >>= 1) {
            float op = __shfl_xor_sync(FULL, p, j);
            int   oo = __shfl_xor_sync(FULL, oe, j);
            bool dirDesc   = ((l16 & kk) == 0) || (kk == 16);
            bool iAmLower  = ((l16 & j) == 0);
            bool mineGreat = (p > op) || (p == op && oe < oo);
            bool keepMine  = dirDesc ? (iAmLower ? mineGreat : !mineGreat)
                                     : (iAmLower ? !mineGreat : mineGreat);
            if (!keepMine) { p = op; oe = oo; }
        }
    }

    // ---- inclusive prefix sum over 16-lane groups ----
    float cum = p;
#pragma unroll
    for (int off = 1; off < 16; off <<= 1) {
        float v = __shfl_up_sync(FULL, cum, off, 16);
        if (l16 >= off) cum += v;
    }
    // ---- dynamic k ----
    unsigned tmmask = __ballot_sync(FULL, cum >= 0.8f) & 0xFFFFu;
    int k = tmmask ? __ffs(tmmask) : 16;       // __ffs is 1-based -> k directly
    float csum = __shfl_sync(FULL, cum, k - 1, 16);

    bool  sel = (l16 < k);
    float w   = sel ? (p / csum) : 0.f;

    // scatter per-expert weights (oe over lanes 0..15 is a permutation)
    if (lane < 16) g_weights[(size_t)tok * NE + oe] = w;

    unsigned bits = __reduce_or_sync(FULL, sel ? (1u << oe) : 0u);
    if (lane == 0) g_maskbits[tok] = bits;

    __syncthreads();
    if (threadIdx.x < NE) {
        int b = tok / NN;                      // same b for all warps in block
        atomicAdd(&g_proxysum[b * NE + threadIdx.x], psum[threadIdx.x]);
    }
}

// ---------------- per-(b,e) capacity prefix scan over tokens ----------------
__global__ void scan_kernel() {
    int b = blockIdx.x / NE;
    int e = blockIdx.x % NE;
    int t = threadIdx.x;                    // 256 threads, 8 tokens each
    __shared__ int s[256];

    unsigned m[8];
    int local = 0;
    int base = b * NN + t * 8;
#pragma unroll
    for (int i = 0; i < 8; i++) { m[i] = (g_maskbits[base + i] >> e) & 1u; local += (int)m[i]; }
    s[t] = local;
    __syncthreads();
    for (int off = 1; off < 256; off <<= 1) {
        int v = (t >= off) ? s[t - off] : 0;
        __syncthreads();
        s[t] += v;
        __syncthreads();
    }
    int excl  = s[t] - local;
    int total = s[255];

    int p = excl;
#pragma unroll
    for (int i = 0; i < 8; i++) {
        size_t idx = (size_t)(base + i) * NE + e;
        if (m[i]) { g_pos[idx] = (p < CAPV) ? p : -1; p++; }
        else        g_pos[idx] = -1;
    }
    if (t == 0) g_dcount[b * NE + e] = (float)min(total, CAPV);
}

// ---------------- scatter tokens into expert input slots (half2 atomics) ----------------
__global__ void scatter_kernel(const float* __restrict__ x) {
    int tok = blockIdx.x;
    int t   = threadIdx.x;                  // 128 threads, 4 values each
    __shared__ int pos[NE];
    __shared__ int ptok;
    if (t < NE) pos[t] = g_pos[(size_t)tok * NE + t];
    __syncthreads();
    if (t == 0) {
        int sp = 0;
        for (int e = 0; e < NE; e++) if (pos[e] >= 0) sp += pos[e];
        ptok = sp;
    }
    __syncthreads();
    int pt = ptok;
    if (pt >= CAPV) return;                 // token dropped entirely
    int b = tok / NN;
    // high-water mark for dead-tile skipping in the GEMMs
    if (t < NE && pos[t] >= 0) atomicMax(&g_hw[t * NB + b], pt + 1);
    const float* xr = x + (size_t)tok * DIMV;
    float4 xv = *(const float4*)&xr[t * 4];
    __half2 h01 = __floats2half2_rn(xv.x, xv.y);
    __half2 h23 = __floats2half2_rn(xv.z, xv.w);
#pragma unroll 1
    for (int e = 0; e < NE; e++) {
        if (pos[e] < 0) continue;
        __half2* dst = (__half2*)(g_ei + (((size_t)e * NB + b) * CAPV + pt) * DIMV + t * 4);
        atomicAdd(dst + 0, h01);
        atomicAdd(dst + 1, h23);
    }
}

// ================= fp16 mma.sync batched GEMM =================
__device__ __forceinline__ void mma_f16(float* c, const unsigned* a, const unsigned* b) {
    asm volatile(
        "mma.sync.aligned.m16n8k16.row.col.f32.f16.f16.f32 "
        "{%0,%1,%2,%3}, {%4,%5,%6,%7}, {%8,%9}, {%0,%1,%2,%3};"
        : "+f"(c[0]), "+f"(c[1]), "+f"(c[2]), "+f"(c[3])
        : "r"(a[0]), "r"(a[1]), "r"(a[2]), "r"(a[3]), "r"(b[0]), "r"(b[1]));
}

template <bool STAGE1>
__global__ __launch_bounds__(256, 2) void gemm_f16_kernel() {
    constexpr int N_out = STAGE1 ? HIDV : DIMV;
    constexpr int K     = STAGE1 ? DIMV : HIDV;
    constexpr int CHUNKS = K / 32;
    const __half* __restrict__ A  = STAGE1 ? g_ei  : g_hidden;
    const __half* __restrict__ Bt = STAGE1 ? g_w1h : g_w2h;    // [E][N_out][K] K-major

    const int e    = blockIdx.z;
    const int row0 = blockIdx.y * 128;

    // ---- dead-tile skip: rows >= hw(e,b) are never read by combine ----
    // tile covers b = blockIdx.y/2, slots [(blockIdx.y&1)*128, +128)
    {
        int b = blockIdx.y >> 1;
        int slot0 = (blockIdx.y & 1) * 128;
        if (slot0 >= g_hw[e * NB + b]) return;
    }

    const int col0 = blockIdx.x * 128;

    const __half* Ae  = A  + (size_t)e * ROWS * K + (size_t)row0 * K;
    const __half* Bte = Bt + (size_t)e * (size_t)N_out * K + (size_t)col0 * K;

    __shared__ __align__(16) __half2 As2[128][20];   // [m][k-half2], 40-half rows
    __shared__ __align__(16) __half2 Bs2[128][20];   // [n][k-half2]

    const int tid  = threadIdx.x;          // 256
    const int lane = tid & 31;
    const int wid  = tid >> 5;
    const int warp_m = wid & 3;            // 32-row strip
    const int warp_n = wid >> 2;           // 64-col strip
    const int qr   = lane >> 2;            // 0..7
    const int qc   = lane & 3;             // 0..3

    float acc[2][8][4];
#pragma unroll
    for (int mt = 0; mt < 2; mt++)
#pragma unroll
        for (int nt = 0; nt < 8; nt++)
#pragma unroll
            for (int i = 0; i < 4; i++) acc[mt][nt][i] = 0.f;

    auto store_tile = [&](__half2 (*Sm)[20], const uint4* v) {
#pragma unroll
        for (int i = 0; i < 2; i++) {
            int idx = i * 256 + tid;           // 0..511
            int r = idx >> 2, q = idx & 3;     // row, uint4-in-row
            const __half2* pv = (const __half2*)&v[i];
#pragma unroll
            for (int j = 0; j < 4; j++) Sm[r][q * 4 + j] = pv[j];
        }
    };
    auto load_tile = [&](const __half* src, int K_, int k0, uint4* v) {
#pragma unroll
        for (int i = 0; i < 2; i++) {
            int idx = i * 256 + tid;
            int r = idx >> 2, q = idx & 3;
            v[i] = *(const uint4*)&src[(size_t)r * K_ + k0 + q * 8];
        }
    };

    uint4 va[2], vb[2];
    load_tile(Ae, K, 0, va);
    load_tile(Bte, K, 0, vb);
    store_tile(As2, va);
    store_tile(Bs2, vb);
    __syncthreads();

    for (int c = 0; c < CHUNKS; c++) {
        const bool has_next = (c + 1) < CHUNKS;
        if (has_next) {
            load_tile(Ae, K, (c + 1) * 32, va);
            load_tile(Bte, K, (c + 1) * 32, vb);
        }

        // compute current chunk: 2 k16 steps
#pragma unroll
        for (int kk = 0; kk < 2; kk++) {
            const int k8 = kk * 8;             // half2 offset of this k16 step
            unsigned a[2][4];
#pragma unroll
            for (int mt = 0; mt < 2; mt++) {
                int r = warp_m * 32 + mt * 16 + qr;
                a[mt][0] = *(const unsigned*)&As2[r    ][k8 + qc];
                a[mt][1] = *(const unsigned*)&As2[r + 8][k8 + qc];
                a[mt][2] = *(const unsigned*)&As2[r    ][k8 + qc + 4];
                a[mt][3] = *(const unsigned*)&As2[r + 8][k8 + qc + 4];
            }
            unsigned b[8][2];
#pragma unroll
            for (int nt = 0; nt < 8; nt++) {
                int n = warp_n * 64 + nt * 8 + qr;
                b[nt][0] = *(const unsigned*)&Bs2[n][k8 + qc];
                b[nt][1] = *(const unsigned*)&Bs2[n][k8 + qc + 4];
            }
#pragma unroll
            for (int mt = 0; mt < 2; mt++)
#pragma unroll
                for (int nt = 0; nt < 8; nt++)
                    mma_f16(acc[mt][nt], a[mt], b[nt]);
        }
        __syncthreads();

        if (has_next) {
            store_tile(As2, va);
            store_tile(Bs2, vb);
            __syncthreads();
        }
    }

    // ---- epilogue ----
    if (STAGE1) {
        __half* Ch = g_hidden + (size_t)e * ROWS * (size_t)N_out;
#pragma unroll
        for (int mt = 0; mt < 2; mt++) {
#pragma unroll
            for (int nt = 0; nt < 8; nt++) {
                int row = row0 + warp_m * 32 + mt * 16 + qr;
                int col = col0 + warp_n * 64 + nt * 8 + qc * 2;
                float v0 = acc[mt][nt][0], v1 = acc[mt][nt][1];
                float v2 = acc[mt][nt][2], v3 = acc[mt][nt][3];
                v0 = v0 * 0.5f * (1.f + erff(v0 * 0.70710678118654752440f));
                v1 = v1 * 0.5f * (1.f + erff(v1 * 0.70710678118654752440f));
                v2 = v2 * 0.5f * (1.f + erff(v2 * 0.70710678118654752440f));
                v3 = v3 * 0.5f * (1.f + erff(v3 * 0.70710678118654752440f));
                *(__half2*)&Ch[(size_t)row * N_out + col]       = __floats2half2_rn(v0, v1);
                *(__half2*)&Ch[(size_t)(row + 8) * N_out + col] = __floats2half2_rn(v2, v3);
            }
        }
    } else {
        float* Cf = g_eo + (size_t)e * ROWS * (size_t)N_out;
#pragma unroll
        for (int mt = 0; mt < 2; mt++) {
#pragma unroll
            for (int nt = 0; nt < 8; nt++) {
                int row = row0 + warp_m * 32 + mt * 16 + qr;
                int col = col0 + warp_n * 64 + nt * 8 + qc * 2;
                float2 lo = {acc[mt][nt][0], acc[mt][nt][1]};
                float2 hi = {acc[mt][nt][2], acc[mt][nt][3]};
                *(float2*)&Cf[(size_t)row * N_out + col]       = lo;
                *(float2*)&Cf[(size_t)(row + 8) * N_out + col] = hi;
            }
        }
    }
}

// ---------------- combine (gather) ----------------
__global__ void combine_kernel(float* __restrict__ out) {
    int tok = blockIdx.x;
    int t   = threadIdx.x;                  // 128 threads, 4 floats each
    __shared__ int   pos[NE];
    __shared__ float w[NE];
    __shared__ int   ptok;
    if (t < NE) {
        pos[t] = g_pos[(size_t)tok * NE + t];
        w[t]   = g_weights[(size_t)tok * NE + t];
    }
    __syncthreads();
    if (t == 0) {
        int sp = 0;
        for (int e = 0; e < NE; e++) if (pos[e] >= 0) sp += pos[e];
        ptok = sp;
    }
    __syncthreads();
    int pt = ptok;
    int b  = tok / NN;
    float4 acc = {0.f, 0.f, 0.f, 0.f};
    if (pt < CAPV) {
#pragma unroll 1
        for (int e = 0; e < NE; e++) {
            if (pos[e] < 0) continue;
            const float4 v =
                *(const float4*)&g_eo[(((size_t)e * NB + b) * CAPV + pt) * DIMV + t * 4];
            float we = w[e];
            acc.x += we * v.x; acc.y += we * v.y;
            acc.z += we * v.z; acc.w += we * v.w;
        }
    }
    *(float4*)&out[(size_t)tok * DIMV + t * 4] = acc;
}

// ---------------- loss (fills ALL trailing elements past the main output) ----------------
__global__ void loss_kernel(float* __restrict__ out, int out_size) {
    int t = threadIdx.x;                    // 128 = NB*NE
    float v = (g_proxysum[t] / (float)NN) * (g_dcount[t] / (float)NN);
    __shared__ float s[128];
    s[t] = v;
    __syncthreads();
    for (int off = 64; off > 0; off >>= 1) {
        if (t < off) s[t] += s[t + off];
        __syncthreads();
    }
    if (t == 0) {
        float loss = (s[0] / 128.f) * (float)(NE * NE) * 0.01f;
        for (size_t i = (size_t)TOK * DIMV; i < (size_t)out_size; i++) out[i] = loss;
    }
}

extern "C" void kernel_launch(void* const* d_in, const int* in_sizes, int n_in,
                              void* d_out, int out_size) {
    // Resolve inputs by element count where unique; w1/w2 keep declaration order.
    const float *x = nullptr, *wg = nullptr, *w1 = nullptr, *w2 = nullptr;
    for (int i = 0; i < n_in; i++) {
        long sz = in_sizes[i];
        if (sz == DIMV * NE)                       wg = (const float*)d_in[i];
        else if (sz == (long)NB * NN * DIMV)       x  = (const float*)d_in[i];
        else if (sz == (long)NE * DIMV * HIDV) {
            if (!w1) w1 = (const float*)d_in[i];
            else     w2 = (const float*)d_in[i];
        }
    }
    float* out = (float*)d_out;

    // 1. zero scratch (g_ei halves: 2,097,152 uint4) + hw + proxysum
    zero_kernel<<<8192, 256>>>();
    // 1b. weight transposes fp32 -> half, K-major
    transpose_kernel<1><<<dim3(HIDV / 32, DIMV / 32, NE), dim3(32, 8)>>>(w1);
    transpose_kernel<2><<<dim3(DIMV / 32, HIDV / 32, NE), dim3(32, 8)>>>(w2);
    // 2. gating (warp per token, smem-staged x)
    gate_kernel<<<TOK / 8, 256>>>(x, wg);
    // 3. capacity scan per (b,e)
    scan_kernel<<<NB * NE, 256>>>();
    // 4. scatter token rows into expert inputs (half2 atomics) + hw marks
    scatter_kernel<<<TOK, 128>>>(x);
    // 5. GEMM1 + GELU (fp16 mma.sync, dead-tile skip)
    gemm_f16_kernel<true><<<dim3(HIDV / 128, ROWS / 128, NE), 256>>>();
    // 6. GEMM2 (fp16 mma.sync, dead-tile skip)
    gemm_f16_kernel<false><<<dim3(DIMV / 128, ROWS / 128, NE), 256>>>();
    // 7. combine
    combine_kernel<<<TOK, 128>>>(out);
    // 8. loss scalar(s)
    loss_kernel<<<1, 128>>>(out, out_size);
}

// round 17
// speedup vs baseline: 1.0426x; 1.0426x over previous
#include <cuda_runtime.h>
#include <cuda_fp16.h>
#include <math.h>
#include <stdint.h>

#define DIMV 512
#define HIDV 2048
#define NE 16
#define NB 8
#define NN 2048
#define CAPV 256
#define TOK (NB*NN)          // 16384
#define ROWS (NB*CAPV)       // 2048 rows per expert

// ---- static device scratch (no dynamic allocations allowed) ----
__device__ __align__(256) __half g_ei[(size_t)NE*ROWS*DIMV];       // 32 MiB (half)
__device__ __align__(256) __half g_hidden[(size_t)NE*ROWS*HIDV];   // 128 MiB (half)
__device__ __align__(256) float  g_eo[(size_t)NE*ROWS*DIMV];       // 64 MiB
__device__ __align__(256) float  g_weights[(size_t)TOK*NE];
__device__ __align__(256) unsigned int g_maskbits[TOK];
__device__ __align__(256) int    g_pos[(size_t)TOK*NE];
__device__ __align__(256) float  g_proxysum[NB*NE];
__device__ __align__(256) float  g_dcount[NB*NE];
__device__ __align__(256) int    g_hw[NE*NB];       // high-water mark per (e,b): max pos_tok+1

__device__ __forceinline__ uint32_t smem_u32(const void* p) {
    uint32_t a;
    asm("{ .reg .u64 t; cvta.to.shared.u64 t, %1; cvt.u32.u64 %0, t; }" : "=r"(a) : "l"(p));
    return a;
}

// ---------------- zero scratch ----------------
// g_ei = 16,777,216 halves = 2,097,152 uint4 -> grid 8192 x 256
__global__ void zero_kernel() {
    size_t i = (size_t)blockIdx.x * blockDim.x + threadIdx.x;
    uint4 z = {0u, 0u, 0u, 0u};
    ((uint4*)g_ei)[i] = z;
    if (i < NB*NE) { g_proxysum[i] = 0.f; g_hw[i] = 0; }
}

// ---------------- gating: one warp per token, smem-staged x ----------------
// Block = 256 threads = 8 warps = 8 tokens. Lane layout: e = lane&15, h = lane>>4.
__global__ __launch_bounds__(256) void gate_kernel(const float* __restrict__ x,
                                                   const float* __restrict__ wg) {
    const int wid   = threadIdx.x >> 5;
    const int lane  = threadIdx.x & 31;
    const int tok   = blockIdx.x * 8 + wid;
    const int e     = lane & 15;             // expert handled by this lane
    const int h     = lane >> 4;             // dim-half
    const unsigned FULL = 0xffffffffu;

    __shared__ float xs[8][DIMV];            // 16 KB: 8 token rows
    __shared__ float psum[NE];               // block-level proxy accumulation
    if (threadIdx.x < NE) psum[threadIdx.x] = 0.f;

    // coalesced block load of 8 rows (1024 float4)
    {
        const float4* xsrc = (const float4*)(x + (size_t)blockIdx.x * 8 * DIMV);
        float4* xdst = (float4*)&xs[0][0];
#pragma unroll
        for (int i = 0; i < 4; i++)
            xdst[threadIdx.x + i * 256] = xsrc[threadIdx.x + i * 256];
    }
    __syncthreads();

    // ---- logits: each lane: sum over 256 dims of x[d]*wg[d][e] ----
    const float4* xrow = (const float4*)&xs[wid][h * 256];
    const float* wgh = wg + (size_t)h * 256 * NE + e;
    float acc = 0.f;
#pragma unroll 8
    for (int i = 0; i < 64; i++) {
        float4 xv = xrow[i];
        const float* wr = wgh + i * 4 * NE;
        acc += xv.x * wr[0 * NE] + xv.y * wr[1 * NE]
             + xv.z * wr[2 * NE] + xv.w * wr[3 * NE];
    }
    acc += __shfl_xor_sync(FULL, acc, 16);   // both halves now hold logit[e]

    // ---- softmax over 16 lanes (halves mirrored) ----
    float mx = acc;
#pragma unroll
    for (int off = 8; off >= 1; off >>= 1)
        mx = fmaxf(mx, __shfl_xor_sync(FULL, mx, off));
    float raw = expf(acc - mx);
    float ssum = raw;
#pragma unroll
    for (int off = 8; off >= 1; off >>= 1)
        ssum += __shfl_xor_sync(FULL, ssum, off);
    raw /= ssum;                              // raw prob for expert e

    // block-level proxy accumulation (all tokens in block share same b)
    if (lane < NE) atomicAdd(&psum[e], raw);

    // ---- bitonic sort, 16 lanes, stable-descending (tie-break on index) ----
    float p = raw;
    int   oe = e;
    const int l16 = lane & 15;
#pragma unroll
    for (int kk = 2; kk <= 16; kk <<= 1) {
#pragma unroll
        for (int j = kk >> 1; j >= 1; j >>= 1) {
            float op = __shfl_xor_sync(FULL, p, j);
            int   oo = __shfl_xor_sync(FULL, oe, j);
            bool dirDesc   = ((l16 & kk) == 0) || (kk == 16);
            bool iAmLower  = ((l16 & j) == 0);
            bool mineGreat = (p > op) || (p == op && oe < oo);
            bool keepMine  = dirDesc ? (iAmLower ? mineGreat : !mineGreat)
                                     : (iAmLower ? !mineGreat : mineGreat);
            if (!keepMine) { p = op; oe = oo; }
        }
    }

    // ---- inclusive prefix sum over 16-lane groups ----
    float cum = p;
#pragma unroll
    for (int off = 1; off < 16; off <<= 1) {
        float v = __shfl_up_sync(FULL, cum, off, 16);
        if (l16 >= off) cum += v;
    }
    // ---- dynamic k ----
    unsigned tmmask = __ballot_sync(FULL, cum >= 0.8f) & 0xFFFFu;
    int k = tmmask ? __ffs(tmmask) : 16;       // __ffs is 1-based -> k directly
    float csum = __shfl_sync(FULL, cum, k - 1, 16);

    bool  sel = (l16 < k);
    float w   = sel ? (p / csum) : 0.f;

    // scatter per-expert weights (oe over lanes 0..15 is a permutation)
    if (lane < 16) g_weights[(size_t)tok * NE + oe] = w;

    unsigned bits = __reduce_or_sync(FULL, sel ? (1u << oe) : 0u);
    if (lane == 0) g_maskbits[tok] = bits;

    __syncthreads();
    if (threadIdx.x < NE) {
        int b = tok / NN;                      // same b for all warps in block
        atomicAdd(&g_proxysum[b * NE + threadIdx.x], psum[threadIdx.x]);
    }
}

// ---------------- per-(b,e) capacity prefix scan over tokens ----------------
__global__ void scan_kernel() {
    int b = blockIdx.x / NE;
    int e = blockIdx.x % NE;
    int t = threadIdx.x;                    // 256 threads, 8 tokens each
    __shared__ int s[256];

    unsigned m[8];
    int local = 0;
    int base = b * NN + t * 8;
#pragma unroll
    for (int i = 0; i < 8; i++) { m[i] = (g_maskbits[base + i] >> e) & 1u; local += (int)m[i]; }
    s[t] = local;
    __syncthreads();
    for (int off = 1; off < 256; off <<= 1) {
        int v = (t >= off) ? s[t - off] : 0;
        __syncthreads();
        s[t] += v;
        __syncthreads();
    }
    int excl  = s[t] - local;
    int total = s[255];

    int p = excl;
#pragma unroll
    for (int i = 0; i < 8; i++) {
        size_t idx = (size_t)(base + i) * NE + e;
        if (m[i]) { g_pos[idx] = (p < CAPV) ? p : -1; p++; }
        else        g_pos[idx] = -1;
    }
    if (t == 0) g_dcount[b * NE + e] = (float)min(total, CAPV);
}

// ---------------- scatter tokens into expert input slots (half2 atomics) ----------------
__global__ void scatter_kernel(const float* __restrict__ x) {
    int tok = blockIdx.x;
    int t   = threadIdx.x;                  // 128 threads, 4 values each
    __shared__ int pos[NE];
    __shared__ int ptok;
    if (t < NE) pos[t] = g_pos[(size_t)tok * NE + t];
    __syncthreads();
    if (t == 0) {
        int sp = 0;
        for (int e = 0; e < NE; e++) if (pos[e] >= 0) sp += pos[e];
        ptok = sp;
    }
    __syncthreads();
    int pt = ptok;
    if (pt >= CAPV) return;                 // token dropped entirely
    int b = tok / NN;
    // high-water mark for dead-tile skipping in the GEMMs
    if (t < NE && pos[t] >= 0) atomicMax(&g_hw[t * NB + b], pt + 1);
    const float* xr = x + (size_t)tok * DIMV;
    float4 xv = *(const float4*)&xr[t * 4];
    __half2 h01 = __floats2half2_rn(xv.x, xv.y);
    __half2 h23 = __floats2half2_rn(xv.z, xv.w);
#pragma unroll 1
    for (int e = 0; e < NE; e++) {
        if (pos[e] < 0) continue;
        __half2* dst = (__half2*)(g_ei + (((size_t)e * NB + b) * CAPV + pt) * DIMV + t * 4);
        atomicAdd(dst + 0, h01);
        atomicAdd(dst + 1, h23);
    }
}

// ================= fp16 mma.sync batched GEMM =================
// B is read DIRECTLY from the harness's row-major fp32 W [E][K][N]:
// tiles stored to smem un-transposed (coalesced), fragments pulled with
// ldmatrix.m8n8.x2.trans (yields the row.col B-frag bitwise-identical to
// the old K-major manual loads). No transpose kernels, no W scratch.
__device__ __forceinline__ void mma_f16(float* c, const unsigned* a, const unsigned* b) {
    asm volatile(
        "mma.sync.aligned.m16n8k16.row.col.f32.f16.f16.f32 "
        "{%0,%1,%2,%3}, {%4,%5,%6,%7}, {%8,%9}, {%0,%1,%2,%3};"
        : "+f"(c[0]), "+f"(c[1]), "+f"(c[2]), "+f"(c[3])
        : "r"(a[0]), "r"(a[1]), "r"(a[2]), "r"(a[3]), "r"(b[0]), "r"(b[1]));
}

#define WS_STRIDE 136   // halves per row (128 + 8 pad): ldmatrix rows hit distinct banks

template <bool STAGE1>
__global__ __launch_bounds__(256, 2) void gemm_f16_kernel(const float* __restrict__ W) {
    constexpr int N_out = STAGE1 ? HIDV : DIMV;
    constexpr int K     = STAGE1 ? DIMV : HIDV;
    constexpr int CHUNKS = K / 32;
    const __half* __restrict__ A = STAGE1 ? g_ei : g_hidden;

    const int e    = blockIdx.z;
    const int row0 = blockIdx.y * 128;

    // ---- dead-tile skip: rows >= hw(e,b) are never read by combine ----
    {
        int b = blockIdx.y >> 1;
        int slot0 = (blockIdx.y & 1) * 128;
        if (slot0 >= g_hw[e * NB + b]) return;
    }

    const int col0 = blockIdx.x * 128;

    const __half* Ae = A + (size_t)e * ROWS * K + (size_t)row0 * K;
    const float*  We = W + (size_t)e * (size_t)K * N_out;

    __shared__ __align__(16) __half2 As2[128][20];       // [m][k-half2], 40-half rows
    __shared__ __align__(16) __half  Ws[32][WS_STRIDE];  // [k][n] row-major

    const int tid  = threadIdx.x;          // 256
    const int lane = tid & 31;
    const int wid  = tid >> 5;
    const int warp_m = wid & 3;            // 32-row strip
    const int warp_n = wid >> 2;           // 64-col strip
    const int qr   = lane >> 2;            // 0..7
    const int qc   = lane & 3;             // 0..3

    const uint32_t ws_base = smem_u32(&Ws[0][0]);
    const uint32_t ldm_row = ws_base + (uint32_t)((lane & 15) * WS_STRIDE) * 2
                           + (uint32_t)(warp_n * 64) * 2;

    float acc[2][8][4];
#pragma unroll
    for (int mt = 0; mt < 2; mt++)
#pragma unroll
        for (int nt = 0; nt < 8; nt++)
#pragma unroll
            for (int i = 0; i < 4; i++) acc[mt][nt][i] = 0.f;

    auto store_A = [&](const uint4* v) {
#pragma unroll
        for (int i = 0; i < 2; i++) {
            int idx = i * 256 + tid;           // 0..511
            int r = idx >> 2, q = idx & 3;     // row, uint4-in-row
            const __half2* pv = (const __half2*)&v[i];
#pragma unroll
            for (int j = 0; j < 4; j++) As2[r][q * 4 + j] = pv[j];
        }
    };
    auto load_A = [&](int k0, uint4* v) {
#pragma unroll
        for (int i = 0; i < 2; i++) {
            int idx = i * 256 + tid;
            int r = idx >> 2, q = idx & 3;
            v[i] = *(const uint4*)&Ae[(size_t)r * K + k0 + q * 8];
        }
    };
    // B tile: 32 k-rows x 128 n-cols fp32 from W[k0+k][col0+n] (coalesced)
    auto load_B = [&](int k0, float4* v) {
#pragma unroll
        for (int i = 0; i < 4; i++) {
            int idx = i * 256 + tid;           // 0..1023
            int kr = idx >> 5, n4 = idx & 31;
            v[i] = *(const float4*)&We[(size_t)(k0 + kr) * N_out + col0 + n4 * 4];
        }
    };
    auto store_B = [&](const float4* v) {
#pragma unroll
        for (int i = 0; i < 4; i++) {
            int idx = i * 256 + tid;
            int kr = idx >> 5, n4 = idx & 31;
            *(__half2*)&Ws[kr][n4 * 4]     = __floats2half2_rn(v[i].x, v[i].y);
            *(__half2*)&Ws[kr][n4 * 4 + 2] = __floats2half2_rn(v[i].z, v[i].w);
        }
    };

    uint4  va[2];
    float4 vb[4];
    load_A(0, va);
    load_B(0, vb);
    store_A(va);
    store_B(vb);
    __syncthreads();

    for (int c = 0; c < CHUNKS; c++) {
        const bool has_next = (c + 1) < CHUNKS;
        if (has_next) {
            load_A((c + 1) * 32, va);
            load_B((c + 1) * 32, vb);
        }

        // compute current chunk: 2 k16 steps
#pragma unroll
        for (int kk = 0; kk < 2; kk++) {
            const int k8 = kk * 8;             // half2 offset of this k16 step
            unsigned a[2][4];
#pragma unroll
            for (int mt = 0; mt < 2; mt++) {
                int r = warp_m * 32 + mt * 16 + qr;
                a[mt][0] = *(const unsigned*)&As2[r    ][k8 + qc];
                a[mt][1] = *(const unsigned*)&As2[r + 8][k8 + qc];
                a[mt][2] = *(const unsigned*)&As2[r    ][k8 + qc + 4];
                a[mt][3] = *(const unsigned*)&As2[r + 8][k8 + qc + 4];
            }
            unsigned b[8][2];
#pragma unroll
            for (int nt = 0; nt < 8; nt++) {
                uint32_t addr = ldm_row + (uint32_t)(kk * 16 * WS_STRIDE + nt * 8) * 2;
                asm volatile(
                    "ldmatrix.sync.aligned.m8n8.x2.trans.shared.b16 {%0,%1}, [%2];"
                    : "=r"(b[nt][0]), "=r"(b[nt][1]) : "r"(addr));
            }
#pragma unroll
            for (int mt = 0; mt < 2; mt++)
#pragma unroll
                for (int nt = 0; nt < 8; nt++)
                    mma_f16(acc[mt][nt], a[mt], b[nt]);
        }
        __syncthreads();

        if (has_next) {
            store_A(va);
            store_B(vb);
            __syncthreads();
        }
    }

    // ---- epilogue ----
    if (STAGE1) {
        __half* Ch = g_hidden + (size_t)e * ROWS * (size_t)N_out;
#pragma unroll
        for (int mt = 0; mt < 2; mt++) {
#pragma unroll
            for (int nt = 0; nt < 8; nt++) {
                int row = row0 + warp_m * 32 + mt * 16 + qr;
                int col = col0 + warp_n * 64 + nt * 8 + qc * 2;
                float v0 = acc[mt][nt][0], v1 = acc[mt][nt][1];
                float v2 = acc[mt][nt][2], v3 = acc[mt][nt][3];
                v0 = v0 * 0.5f * (1.f + erff(v0 * 0.70710678118654752440f));
                v1 = v1 * 0.5f * (1.f + erff(v1 * 0.70710678118654752440f));
                v2 = v2 * 0.5f * (1.f + erff(v2 * 0.70710678118654752440f));
                v3 = v3 * 0.5f * (1.f + erff(v3 * 0.70710678118654752440f));
                *(__half2*)&Ch[(size_t)row * N_out + col]       = __floats2half2_rn(v0, v1);
                *(__half2*)&Ch[(size_t)(row + 8) * N_out + col] = __floats2half2_rn(v2, v3);
            }
        }
    } else {
        float* Cf = g_eo + (size_t)e * ROWS * (size_t)N_out;
#pragma unroll
        for (int mt = 0; mt < 2; mt++) {
#pragma unroll
            for (int nt = 0; nt < 8; nt++) {
                int row = row0 + warp_m * 32 + mt * 16 + qr;
                int col = col0 + warp_n * 64 + nt * 8 + qc * 2;
                float2 lo = {acc[mt][nt][0], acc[mt][nt][1]};
                float2 hi = {acc[mt][nt][2], acc[mt][nt][3]};
                *(float2*)&Cf[(size_t)row * N_out + col]       = lo;
                *(float2*)&Cf[(size_t)(row + 8) * N_out + col] = hi;
            }
        }
    }
}

// ---------------- combine (gather) ----------------
__global__ void combine_kernel(float* __restrict__ out) {
    int tok = blockIdx.x;
    int t   = threadIdx.x;                  // 128 threads, 4 floats each
    __shared__ int   pos[NE];
    __shared__ float w[NE];
    __shared__ int   ptok;
    if (t < NE) {
        pos[t] = g_pos[(size_t)tok * NE + t];
        w[t]   = g_weights[(size_t)tok * NE + t];
    }
    __syncthreads();
    if (t == 0) {
        int sp = 0;
        for (int e = 0; e < NE; e++) if (pos[e] >= 0) sp += pos[e];
        ptok = sp;
    }
    __syncthreads();
    int pt = ptok;
    int b  = tok / NN;
    float4 acc = {0.f, 0.f, 0.f, 0.f};
    if (pt < CAPV) {
#pragma unroll 1
        for (int e = 0; e < NE; e++) {
            if (pos[e] < 0) continue;
            const float4 v =
                *(const float4*)&g_eo[(((size_t)e * NB + b) * CAPV + pt) * DIMV + t * 4];
            float we = w[e];
            acc.x += we * v.x; acc.y += we * v.y;
            acc.z += we * v.z; acc.w += we * v.w;
        }
    }
    *(float4*)&out[(size_t)tok * DIMV + t * 4] = acc;
}

// ---------------- loss (fills ALL trailing elements past the main output) ----------------
__global__ void loss_kernel(float* __restrict__ out, int out_size) {
    int t = threadIdx.x;                    // 128 = NB*NE
    float v = (g_proxysum[t] / (float)NN) * (g_dcount[t] / (float)NN);
    __shared__ float s[128];
    s[t] = v;
    __syncthreads();
    for (int off = 64; off > 0; off >>= 1) {
        if (t < off) s[t] += s[t + off];
        __syncthreads();
    }
    if (t == 0) {
        float loss = (s[0] / 128.f) * (float)(NE * NE) * 0.01f;
        for (size_t i = (size_t)TOK * DIMV; i < (size_t)out_size; i++) out[i] = loss;
    }
}

extern "C" void kernel_launch(void* const* d_in, const int* in_sizes, int n_in,
                              void* d_out, int out_size) {
    // Resolve inputs by element count where unique; w1/w2 keep declaration order.
    const float *x = nullptr, *wg = nullptr, *w1 = nullptr, *w2 = nullptr;
    for (int i = 0; i < n_in; i++) {
        long sz = in_sizes[i];
        if (sz == DIMV * NE)                       wg = (const float*)d_in[i];
        else if (sz == (long)NB * NN * DIMV)       x  = (const float*)d_in[i];
        else if (sz == (long)NE * DIMV * HIDV) {
            if (!w1) w1 = (const float*)d_in[i];
            else     w2 = (const float*)d_in[i];
        }
    }
    float* out = (float*)d_out;

    // 1. zero scratch (g_ei halves: 2,097,152 uint4) + hw + proxysum
    zero_kernel<<<8192, 256>>>();
    // 2. gating (warp per token, smem-staged x)
    gate_kernel<<<TOK / 8, 256>>>(x, wg);
    // 3. capacity scan per (b,e)
    scan_kernel<<<NB * NE, 256>>>();
    // 4. scatter token rows into expert inputs (half2 atomics) + hw marks
    scatter_kernel<<<TOK, 128>>>(x);
    // 5. GEMM1 + GELU (fp16 mma.sync, W row-major via ldmatrix.trans)
    gemm_f16_kernel<true><<<dim3(HIDV / 128, ROWS / 128, NE), 256>>>(w1);
    // 6. GEMM2 (fp16 mma.sync, W row-major via ldmatrix.trans)
    gemm_f16_kernel<false><<<dim3(DIMV / 128, ROWS / 128, NE), 256>>>(w2);
    // 7. combine
    combine_kernel<<<TOK, 128>>>(out);
    // 8. loss scalar(s)
    loss_kernel<<<1, 128>>>(out, out_size);
}